// round 7
// baseline (speedup 1.0000x reference)
#include <cuda_runtime.h>
#include <cstdint>

// VectorQuantizer: input (16, 64, 8192) fp32, codebook (1024, 64) fp32
// score(n,k) = 0.5*||e_k||^2 - x_n . e_k   (argmin-equivalent to ||x - e||^2)
//
// R7 = R6 inner loop (2 tokens/thread, 16 LDS.128 : 64 FFMA2 per code,
// cp.async double buffer, no spills) with finer CTA granularity:
// TPB=64, 128 tokens/CTA, grid=1024, 6 CTAs/SM -> wave tail 15% -> ~1%.

#define Dd 64
#define Kk 1024
#define Bb 16
#define Tt 8192
#define Nn (Bb * Tt)            // 131072 tokens
#define TPB 64
#define TOK_PER_CTA 128         // 2 tokens per thread
#define CK 64                   // codes per smem chunk (64*64*4 = 16 KB)
#define NCHUNK (Kk / CK)        // 16

__device__ float g_half[Kk];

// ---- packed f32x2 helpers ----
__device__ __forceinline__ unsigned long long pk2(float a, float b) {
    unsigned long long r;
    asm("mov.b64 %0, {%1, %2};" : "=l"(r) : "f"(a), "f"(b));
    return r;
}
__device__ __forceinline__ void fma2(unsigned long long& acc,
                                     unsigned long long a, unsigned long long b) {
    asm("fma.rn.f32x2 %0, %1, %2, %0;" : "+l"(acc) : "l"(a), "l"(b));
}
__device__ __forceinline__ unsigned long long add2(unsigned long long a,
                                                   unsigned long long b) {
    unsigned long long r;
    asm("add.rn.f32x2 %0, %1, %2;" : "=l"(r) : "l"(a), "l"(b));
    return r;
}
__device__ __forceinline__ float hsum2(unsigned long long v) {
    float lo, hi;
    asm("mov.b64 {%0, %1}, %2;" : "=f"(lo), "=f"(hi) : "l"(v));
    return lo + hi;
}

// ---- cp.async helpers ----
__device__ __forceinline__ void cp16(uint32_t dst, const float* src) {
    uint64_t g = __cvta_generic_to_global((void*)src);
    asm volatile("cp.async.cg.shared.global [%0], [%1], 16;" :: "r"(dst), "l"(g) : "memory");
}
__device__ __forceinline__ void cp_commit() { asm volatile("cp.async.commit_group;" ::: "memory"); }
template <int N>
__device__ __forceinline__ void cp_wait() { asm volatile("cp.async.wait_group %0;" :: "n"(N) : "memory"); }

__device__ __forceinline__ uint32_t s2u(const void* p) {
    uint32_t a;
    asm("{ .reg .u64 t; cvta.to.shared.u64 t, %1; cvt.u32.u64 %0, t; }" : "=r"(a) : "l"(p));
    return a;
}

// Precompute 0.5*||e_k||^2.
__global__ void vq_pre(const float* __restrict__ cb) {
    int k = blockIdx.x * blockDim.x + threadIdx.x;
    if (k >= Kk) return;
    const float4* row = reinterpret_cast<const float4*>(cb + k * Dd);
    float s = 0.f;
#pragma unroll
    for (int i = 0; i < Dd / 4; i++) {
        float4 v = row[i];
        s += v.x * v.x + v.y * v.y + v.z * v.z + v.w * v.w;
    }
    g_half[k] = 0.5f * s;
}

__global__ __launch_bounds__(TPB, 6)
void vq_main(const float* __restrict__ input, const float* __restrict__ cb,
             float* __restrict__ out, float* __restrict__ out_idx) {
    __shared__ float sCode[2][CK * Dd];   // 2 x 16 KB codebook chunks
    __shared__ float sHalf[Kk];           // 4 KB

    const int tid  = threadIdx.x;
    const int tile = blockIdx.x;                  // 0..1023
    const int b    = tile >> 6;                   // 64 tiles per batch
    const int t0   = ((tile & 63) << 7) + tid;    // token 0 time index
    const int t1   = t0 + TPB;                    // token 1
    const float* inb = input + (size_t)b * Dd * Tt;

    const uint32_t sc0 = s2u(&sCode[0][0]);
    const uint32_t sc1 = s2u(&sCode[1][0]);

    // prefetch codebook chunk 0 into buffer 0 (coalesced 16B copies)
#pragma unroll
    for (int s = 0; s < (CK * Dd / 4) / TPB; s++) {   // 16 slots per thread
        int i = tid + s * TPB;
        cp16(sc0 + i * 16, cb + i * 4);
    }
    cp_commit();

    // load both tokens, packed along D: x[i] = {x[2i], x[2i+1]}
    unsigned long long x0[Dd / 2], x1[Dd / 2];
#pragma unroll
    for (int i = 0; i < Dd / 2; i++) {
        float a0 = inb[(size_t)(2 * i) * Tt + t0];
        float b0 = inb[(size_t)(2 * i + 1) * Tt + t0];
        x0[i] = pk2(a0, b0);
        float a1 = inb[(size_t)(2 * i) * Tt + t1];
        float b1 = inb[(size_t)(2 * i + 1) * Tt + t1];
        x1[i] = pk2(a1, b1);
    }

#pragma unroll
    for (int i = tid; i < Kk; i += TPB) sHalf[i] = g_half[i];

    float best0 = 3.4e38f, best1 = 3.4e38f;
    int bi0 = 0, bi1 = 0;

    for (int c = 0; c < NCHUNK; c++) {
        // prefetch chunk c+1 into the other buffer
        if (c + 1 < NCHUNK) {
            const uint32_t nxt = (c & 1) ? sc0 : sc1;
            const float* src = cb + (size_t)(c + 1) * CK * Dd;
#pragma unroll
            for (int s = 0; s < (CK * Dd / 4) / TPB; s++) {
                int i = tid + s * TPB;
                cp16(nxt + i * 16, src + i * 4);
            }
            cp_commit();
            cp_wait<1>();          // chunk c complete; c+1 still in flight
        } else {
            cp_wait<0>();
        }
        __syncthreads();

        const float* buf = (c & 1) ? &sCode[1][0] : &sCode[0][0];
        const int kbase = c * CK;
#pragma unroll 2
        for (int k = 0; k < CK; k++) {
            const ulonglong2* er = reinterpret_cast<const ulonglong2*>(buf + k * Dd);
            unsigned long long a00 = 0, a01 = 0, a10 = 0, a11 = 0;
#pragma unroll
            for (int j = 0; j < 16; j++) {
                ulonglong2 e = er[j];              // LDS.128 broadcast
                fma2(a00, x0[2 * j],     e.x);
                fma2(a01, x0[2 * j + 1], e.y);
                fma2(a10, x1[2 * j],     e.x);
                fma2(a11, x1[2 * j + 1], e.y);
            }
            const int kk = kbase + k;
            const float hs = sHalf[kk];
            float s0 = hs - hsum2(add2(a00, a01));
            float s1 = hs - hsum2(add2(a10, a11));
            if (s0 < best0) { best0 = s0; bi0 = kk; }   // strict <: first-occurrence ties
            if (s1 < best1) { best1 = s1; bi1 = kk; }
        }
        __syncthreads();   // protect buffer before next prefetch overwrites it
    }

    // scatter selected code vectors back to (B, D, T); coalesced across threads
    float* ob = out + (size_t)b * Dd * Tt;
    const float4* c0 = reinterpret_cast<const float4*>(cb + (size_t)bi0 * Dd);
    const float4* c1 = reinterpret_cast<const float4*>(cb + (size_t)bi1 * Dd);
#pragma unroll
    for (int i = 0; i < Dd / 4; i++) {
        float4 v0 = c0[i];
        float4 v1 = c1[i];
        ob[(size_t)(4 * i + 0) * Tt + t0] = v0.x;
        ob[(size_t)(4 * i + 1) * Tt + t0] = v0.y;
        ob[(size_t)(4 * i + 2) * Tt + t0] = v0.z;
        ob[(size_t)(4 * i + 3) * Tt + t0] = v0.w;
        ob[(size_t)(4 * i + 0) * Tt + t1] = v1.x;
        ob[(size_t)(4 * i + 1) * Tt + t1] = v1.y;
        ob[(size_t)(4 * i + 2) * Tt + t1] = v1.z;
        ob[(size_t)(4 * i + 3) * Tt + t1] = v1.w;
    }

    if (out_idx != nullptr) {
        out_idx[(size_t)b * Tt + t0] = (float)bi0;
        out_idx[(size_t)b * Tt + t1] = (float)bi1;
    }
}

extern "C" void kernel_launch(void* const* d_in, const int* in_sizes, int n_in,
                              void* d_out, int out_size) {
    const float* input = (const float*)d_in[0];   // (16, 64, 8192) fp32
    const float* cb    = (const float*)d_in[1];   // (1024, 64) fp32
    float* out = (float*)d_out;

    float* out_idx = nullptr;
    if (out_size >= (int)((long)Nn * Dd + Nn)) out_idx = out + (long)Nn * Dd;

    vq_pre<<<(Kk + 127) / 128, 128>>>(cb);
    vq_main<<<Nn / TOK_PER_CTA, TPB>>>(input, cb, out, out_idx);
}

// round 8
// speedup vs baseline: 1.1501x; 1.1501x over previous
#include <cuda_runtime.h>
#include <cstdint>

// VectorQuantizer: input (16, 64, 8192) fp32, codebook (1024, 64) fp32
// score(n,k) = 0.5*||e_k||^2 - x_n . e_k   (argmin-equivalent to ||x - e||^2)
//
// R8: register-tiled 8x8 fp32x2 GEMM. Thread tile = 8 tokens x 8 codes,
// X staged in smem, codebook pre-transposed to a padded conflict-free image.
// 8:1 FFMA2:LDS ratio, 64 independent acc chains per thread. Argmin via
// packed u64 (monotone score || index) min + one butterfly at the end.

#define Dd 64
#define Kk 1024
#define Bb 16
#define Tt 8192
#define Nn (Bb * Tt)             // 131072 tokens
#define TPB 128
#define TOK_PER_CTA 128
#define CK 64                    // codes per chunk
#define NCHUNK (Kk / CK)         // 16

#define GSTRIDE 2064             // bytes per 8-entry group: 32 dpairs*64B + 16 pad (== 16 mod 128)
#define CHUNK_BYTES (8 * GSTRIDE)        // 16512
#define XOFF 0                   // X image: 16 groups
#define XBYTES (16 * GSTRIDE)            // 33024
#define EOFF0 XBYTES
#define EOFF1 (EOFF0 + CHUNK_BYTES)      // 49536
#define HOFF  (EOFF1 + CHUNK_BYTES)      // 66048
#define IOFF  (HOFF + 4096)              // 70144
#define SMEM_BYTES (IOFF + 512)          // 70656

__device__ float g_half[Kk];
__device__ __align__(16) unsigned char g_cbT[NCHUNK * CHUNK_BYTES];  // padded transposed codebook

typedef unsigned long long u64;

// ---- packed f32x2 helpers ----
__device__ __forceinline__ u64 pk2(float a, float b) {
    u64 r; asm("mov.b64 %0, {%1, %2};" : "=l"(r) : "f"(a), "f"(b)); return r;
}
__device__ __forceinline__ void fma2(u64& acc, u64 a, u64 b) {
    asm("fma.rn.f32x2 %0, %1, %2, %0;" : "+l"(acc) : "l"(a), "l"(b));
}
__device__ __forceinline__ float hsum2(u64 v) {
    float lo, hi; asm("mov.b64 {%0, %1}, %2;" : "=f"(lo), "=f"(hi) : "l"(v));
    return lo + hi;
}
// order-preserving float -> u32 (exact, bijective)
__device__ __forceinline__ uint32_t mono(float f) {
    uint32_t b = __float_as_uint(f);
    return b ^ (uint32_t)(((int32_t)b >> 31) | 0x80000000);
}

// ---- cp.async helpers ----
__device__ __forceinline__ void cp16(uint32_t dst, const void* src) {
    uint64_t g = __cvta_generic_to_global(src);
    asm volatile("cp.async.cg.shared.global [%0], [%1], 16;" :: "r"(dst), "l"(g) : "memory");
}
__device__ __forceinline__ void cp_commit() { asm volatile("cp.async.commit_group;" ::: "memory"); }
template <int N>
__device__ __forceinline__ void cp_wait() { asm volatile("cp.async.wait_group %0;" :: "n"(N) : "memory"); }

__device__ __forceinline__ uint32_t s2u(const void* p) {
    uint32_t a;
    asm("{ .reg .u64 t; cvta.to.shared.u64 t, %1; cvt.u32.u64 %0, t; }" : "=r"(a) : "l"(p));
    return a;
}

// ---- prologue: 0.5||e||^2 + padded transposed codebook image ----
// chunk c, group g, dpair i, entry j  <-  code k = c*64 + g*8 + j
__global__ void vq_pre(const float* __restrict__ cb) {
    int k = blockIdx.x * blockDim.x + threadIdx.x;
    if (k >= Kk) return;
    const float* row = cb + k * Dd;
    float s = 0.f;
    unsigned char* dst = g_cbT + (k >> 6) * CHUNK_BYTES + ((k >> 3) & 7) * GSTRIDE + (k & 7) * 8;
#pragma unroll
    for (int i = 0; i < 32; i++) {
        float a = row[2 * i], b = row[2 * i + 1];
        s += a * a + b * b;
        *(u64*)(dst + i * 64) = pk2(a, b);
    }
    g_half[k] = 0.5f * s;
}

__global__ __launch_bounds__(TPB, 2)
void vq_main(const float* __restrict__ input, const float* __restrict__ cb,
             float* __restrict__ out, float* __restrict__ out_idx) {
    extern __shared__ __align__(16) unsigned char smem[];
    const uint32_t sb = s2u(smem);

    const int tid = threadIdx.x;
    const int kl  = tid & 7;        // code-group lane (8 codes)
    const int ml  = tid >> 3;       // token-group (8 tokens)
    const int tile = blockIdx.x;    // 0..1023
    const int b    = tile >> 6;
    const int tb   = (tile & 63) * TOK_PER_CTA;

    // prefetch codebook chunk 0
#pragma unroll
    for (int s = 0; s < 9; s++) {
        int idx = tid + s * TPB;
        if (idx < CHUNK_BYTES / 16)
            cp16(sb + EOFF0 + idx * 16, g_cbT + idx * 16);
    }
    cp_commit();

    // stage X tile: token t = tb + tid, packed pairs along D
    {
        const float* inb = input + (size_t)b * Dd * Tt + tb + tid;
        unsigned char* xdst = smem + XOFF + (tid >> 3) * GSTRIDE + (tid & 7) * 8;
#pragma unroll 8
        for (int i = 0; i < 32; i++) {
            float a = inb[(size_t)(2 * i) * Tt];
            float c = inb[(size_t)(2 * i + 1) * Tt];
            *(u64*)(xdst + i * 64) = pk2(a, c);
        }
    }
    // stage 0.5||e||^2
    {
        float* sH = (float*)(smem + HOFF);
#pragma unroll
        for (int i = tid; i < Kk; i += TPB) sH[i] = g_half[i];
    }

    u64 best[8];
#pragma unroll
    for (int m = 0; m < 8; m++) best[m] = 0xFFFFFFFFFFFFFFFFull;

    const unsigned char* Xb = smem + XOFF + ml * GSTRIDE;
    const float* sH = (const float*)(smem + HOFF);

    for (int c = 0; c < NCHUNK; c++) {
        const int st = c & 1;
        if (c + 1 < NCHUNK) {
            const uint32_t nxt = sb + (st ? EOFF0 : EOFF1);
            const unsigned char* src = g_cbT + (size_t)(c + 1) * CHUNK_BYTES;
#pragma unroll
            for (int s = 0; s < 9; s++) {
                int idx = tid + s * TPB;
                if (idx < CHUNK_BYTES / 16)
                    cp16(nxt + idx * 16, src + idx * 16);
            }
            cp_commit();
            cp_wait<1>();
        } else {
            cp_wait<0>();
        }
        __syncthreads();

        const unsigned char* Eb = smem + (st ? EOFF1 : EOFF0) + kl * GSTRIDE;

        u64 acc[8][8];
#pragma unroll
        for (int m = 0; m < 8; m++)
#pragma unroll
            for (int k = 0; k < 8; k++) acc[m][k] = 0;

#pragma unroll 4
        for (int i = 0; i < 32; i++) {
            ulonglong2 x0 = *(const ulonglong2*)(Xb + i * 64);
            ulonglong2 x1 = *(const ulonglong2*)(Xb + i * 64 + 16);
            ulonglong2 x2 = *(const ulonglong2*)(Xb + i * 64 + 32);
            ulonglong2 x3 = *(const ulonglong2*)(Xb + i * 64 + 48);
            ulonglong2 e0 = *(const ulonglong2*)(Eb + i * 64);
            ulonglong2 e1 = *(const ulonglong2*)(Eb + i * 64 + 16);
            ulonglong2 e2 = *(const ulonglong2*)(Eb + i * 64 + 32);
            ulonglong2 e3 = *(const ulonglong2*)(Eb + i * 64 + 48);
            u64 xv[8] = {x0.x, x0.y, x1.x, x1.y, x2.x, x2.y, x3.x, x3.y};
            u64 ev[8] = {e0.x, e0.y, e1.x, e1.y, e2.x, e2.y, e3.x, e3.y};
#pragma unroll
            for (int m = 0; m < 8; m++)
#pragma unroll
                for (int k = 0; k < 8; k++)
                    fma2(acc[m][k], xv[m], ev[k]);
        }

        // fold tile into per-token best keys
        const int cbase = c * CK + kl * 8;
        float hs[8];
#pragma unroll
        for (int k = 0; k < 8; k++) hs[k] = sH[cbase + k];
#pragma unroll
        for (int m = 0; m < 8; m++) {
#pragma unroll
            for (int k = 0; k < 8; k++) {
                float s = hs[k] - hsum2(acc[m][k]);
                u64 key = ((u64)mono(s) << 32) | (uint32_t)(cbase + k);
                if (key < best[m]) best[m] = key;
            }
        }
        __syncthreads();   // protect E buffer before next prefetch lands
    }

    // reduce across the 8 code-lanes (same token rows)
#pragma unroll
    for (int off = 1; off < 8; off <<= 1) {
#pragma unroll
        for (int m = 0; m < 8; m++) {
            u64 o = __shfl_xor_sync(0xffffffffu, best[m], off);
            if (o < best[m]) best[m] = o;
        }
    }
    int* sIdx = (int*)(smem + IOFF);
    if (kl == 0) {
#pragma unroll
        for (int m = 0; m < 8; m++) sIdx[ml * 8 + m] = (int)(best[m] & 0xFFFFFFFFu);
    }
    __syncthreads();

    // scatter: thread tid owns token tb + tid
    {
        const int bidx = sIdx[tid];
        const int t = tb + tid;
        float* ob = out + (size_t)b * Dd * Tt + t;
        const float4* cv = (const float4*)(cb + (size_t)bidx * Dd);
#pragma unroll
        for (int i = 0; i < Dd / 4; i++) {
            float4 v = cv[i];
            ob[(size_t)(4 * i + 0) * Tt] = v.x;
            ob[(size_t)(4 * i + 1) * Tt] = v.y;
            ob[(size_t)(4 * i + 2) * Tt] = v.z;
            ob[(size_t)(4 * i + 3) * Tt] = v.w;
        }
        if (out_idx != nullptr) out_idx[(size_t)b * Tt + t] = (float)bidx;
    }
}

extern "C" void kernel_launch(void* const* d_in, const int* in_sizes, int n_in,
                              void* d_out, int out_size) {
    const float* input = (const float*)d_in[0];   // (16, 64, 8192) fp32
    const float* cb    = (const float*)d_in[1];   // (1024, 64) fp32
    float* out = (float*)d_out;

    float* out_idx = nullptr;
    if (out_size >= (int)((long)Nn * Dd + Nn)) out_idx = out + (long)Nn * Dd;

    cudaFuncSetAttribute(vq_main, cudaFuncAttributeMaxDynamicSharedMemorySize, SMEM_BYTES);

    vq_pre<<<(Kk + 127) / 128, 128>>>(cb);
    vq_main<<<Nn / TOK_PER_CTA, TPB, SMEM_BYTES>>>(input, cb, out, out_idx);
}